// round 1
// baseline (speedup 1.0000x reference)
#include <cuda_runtime.h>
#include <math.h>

// Problem constants
#define N_PIX     8192      // B*H*W = 2*64*64
#define N_TOK     8         // tokens per pixel
#define DIM       512
#define INNER     512       // HEADS*DIM_HEAD
#define INNER3    1536
#define HEADS     8
#define DIM_HEAD  64
#define SCALE_F   0.125f    // 64^-0.5
#define M_ROWS    65536     // N_PIX * N_TOK

// Scratch (allocation-free rule: __device__ globals)
__device__ float g_qkv[(size_t)M_ROWS * INNER3];   // ~402 MB
__device__ float g_att[(size_t)M_ROWS * INNER];    // ~134 MB

// ---------------------------------------------------------------------------
// SGEMM: C[M,N] = A[M,K] @ B[K,N] (+ bias). 128x128 tile, BK=16, 256 threads,
// 8x8 per-thread microtile, float4 global + smem traffic.
// Requires M%128==0, N%128==0, K%16==0 (holds for all three calls).
// ---------------------------------------------------------------------------
template <bool BIAS>
__global__ void __launch_bounds__(256)
sgemm_kernel(const float* __restrict__ A, const float* __restrict__ B,
             const float* __restrict__ bias, float* __restrict__ C,
             int M, int N, int K)
{
    constexpr int BM = 128, BN = 128, BK = 16;
    __shared__ float As[BK][BM];   // transposed A tile
    __shared__ float Bs[BK][BN];

    const int bm  = blockIdx.y * BM;
    const int bn  = blockIdx.x * BN;
    const int tid = threadIdx.x;
    const int tr  = tid >> 4;      // 0..15
    const int tc  = tid & 15;      // 0..15

    float acc[8][8];
#pragma unroll
    for (int i = 0; i < 8; i++)
#pragma unroll
        for (int j = 0; j < 8; j++) acc[i][j] = 0.f;

    for (int k0 = 0; k0 < K; k0 += BK) {
        // A tile: 128 rows x 16 cols = 512 float4 slots, 2 per thread
#pragma unroll
        for (int l = 0; l < 2; l++) {
            int s   = tid * 2 + l;
            int row = s >> 2;
            int c4  = s & 3;
            float4 a = *reinterpret_cast<const float4*>(
                A + (size_t)(bm + row) * K + k0 + c4 * 4);
            As[c4 * 4 + 0][row] = a.x;
            As[c4 * 4 + 1][row] = a.y;
            As[c4 * 4 + 2][row] = a.z;
            As[c4 * 4 + 3][row] = a.w;
        }
        // B tile: 16 rows x 128 cols = 512 float4 slots, 2 per thread
#pragma unroll
        for (int l = 0; l < 2; l++) {
            int s   = tid * 2 + l;
            int row = s >> 5;
            int c4  = s & 31;
            *reinterpret_cast<float4*>(&Bs[row][c4 * 4]) =
                *reinterpret_cast<const float4*>(
                    B + (size_t)(k0 + row) * N + bn + c4 * 4);
        }
        __syncthreads();

#pragma unroll
        for (int k = 0; k < BK; k++) {
            float ar[8], br[8];
            *reinterpret_cast<float4*>(&ar[0]) =
                *reinterpret_cast<const float4*>(&As[k][tr * 8]);
            *reinterpret_cast<float4*>(&ar[4]) =
                *reinterpret_cast<const float4*>(&As[k][tr * 8 + 4]);
            *reinterpret_cast<float4*>(&br[0]) =
                *reinterpret_cast<const float4*>(&Bs[k][tc * 8]);
            *reinterpret_cast<float4*>(&br[4]) =
                *reinterpret_cast<const float4*>(&Bs[k][tc * 8 + 4]);
#pragma unroll
            for (int i = 0; i < 8; i++)
#pragma unroll
                for (int j = 0; j < 8; j++)
                    acc[i][j] = fmaf(ar[i], br[j], acc[i][j]);
        }
        __syncthreads();
    }

    // Epilogue
    float bv[8];
    if (BIAS) {
#pragma unroll
        for (int j = 0; j < 8; j++) bv[j] = bias[bn + tc * 8 + j];
    }
#pragma unroll
    for (int i = 0; i < 8; i++) {
        size_t row = (size_t)(bm + tr * 8 + i);
        float* cp = C + row * N + bn + tc * 8;
        float4 v0, v1;
        v0.x = acc[i][0]; v0.y = acc[i][1]; v0.z = acc[i][2]; v0.w = acc[i][3];
        v1.x = acc[i][4]; v1.y = acc[i][5]; v1.z = acc[i][6]; v1.w = acc[i][7];
        if (BIAS) {
            v0.x += bv[0]; v0.y += bv[1]; v0.z += bv[2]; v0.w += bv[3];
            v1.x += bv[4]; v1.y += bv[5]; v1.z += bv[6]; v1.w += bv[7];
        }
        *reinterpret_cast<float4*>(cp)     = v0;
        *reinterpret_cast<float4*>(cp + 4) = v1;
    }
}

// ---------------------------------------------------------------------------
// Per-pixel attention: one block per pixel. Loads q/k/v [8x512] each into
// smem, computes 8 heads of 8x8 masked softmax attention, writes [8x512].
// Dynamic smem: 3*8*512 + 512 floats = 51200 B.
// ---------------------------------------------------------------------------
__global__ void __launch_bounds__(256)
attn_kernel(const float* __restrict__ qkv, const float* __restrict__ mask,
            float* __restrict__ out)
{
    extern __shared__ float sh[];
    float* sq = sh;            // [8][512]
    float* sk = sh + 4096;     // [8][512]
    float* sv = sh + 8192;     // [8][512]
    float* sd = sh + 12288;    // [8 heads][8][8]

    const int p   = blockIdx.x;
    const int tid = threadIdx.x;
    const float* base = qkv + (size_t)p * N_TOK * INNER3;

    // Load 8 x 1536 floats = 3072 float4, 12 per thread
    for (int s = tid; s < 3072; s += 256) {
        int row = s / 384;
        int c4  = s % 384;
        float4 v = *reinterpret_cast<const float4*>(base + (size_t)row * INNER3 + c4 * 4);
        int col = c4 * 4;
        if (col < 512)       *reinterpret_cast<float4*>(&sq[row * 512 + col])        = v;
        else if (col < 1024) *reinterpret_cast<float4*>(&sk[row * 512 + col - 512])  = v;
        else                 *reinterpret_cast<float4*>(&sv[row * 512 + col - 1024]) = v;
    }
    __syncthreads();

    // Dots: 8 heads * 8 * 8 = 512 dot products of length 64 (2 per thread)
    for (int s = tid; s < 512; s += 256) {
        int h = s >> 6;
        int i = (s >> 3) & 7;
        int j = s & 7;
        const float4* qp = reinterpret_cast<const float4*>(&sq[i * 512 + h * 64]);
        const float4* kp = reinterpret_cast<const float4*>(&sk[j * 512 + h * 64]);
        float acc = 0.f;
#pragma unroll
        for (int d = 0; d < 16; d++) {
            float4 a = qp[d], b = kp[d];
            acc += a.x * b.x + a.y * b.y + a.z * b.z + a.w * b.w;
        }
        float m = mask[(size_t)p * 64 + i * 8 + j];
        sd[(h * 8 + i) * 8 + j] = acc * SCALE_F * m;
    }
    __syncthreads();

    // Softmax over j for each (h, i): 64 rows, one thread each
    if (tid < 64) {
        int h = tid >> 3, i = tid & 7;
        float* row = &sd[(h * 8 + i) * 8];
        float mx = row[0];
#pragma unroll
        for (int j = 1; j < 8; j++) mx = fmaxf(mx, row[j]);
        float e[8];
        float sum = 0.f;
#pragma unroll
        for (int j = 0; j < 8; j++) { e[j] = __expf(row[j] - mx); sum += e[j]; }
        float inv = 1.f / sum;
#pragma unroll
        for (int j = 0; j < 8; j++) row[j] = e[j] * inv;
    }
    __syncthreads();

    // out[i][h*64+d] = sum_j attn[h,i,j] * v[j][h*64+d] : 1024 float4, 4/thread
    float* ob = out + (size_t)p * N_TOK * INNER;
    for (int s = tid; s < 1024; s += 256) {
        int i   = s >> 7;          // token
        int c4  = s & 127;
        int col = c4 * 4;
        int h   = col >> 6;
        float4 acc = make_float4(0.f, 0.f, 0.f, 0.f);
#pragma unroll
        for (int j = 0; j < 8; j++) {
            float a = sd[(h * 8 + i) * 8 + j];
            float4 vv = *reinterpret_cast<const float4*>(&sv[j * 512 + col]);
            acc.x = fmaf(a, vv.x, acc.x);
            acc.y = fmaf(a, vv.y, acc.y);
            acc.z = fmaf(a, vv.z, acc.z);
            acc.w = fmaf(a, vv.w, acc.w);
        }
        *reinterpret_cast<float4*>(ob + (size_t)i * INNER + col) = acc;
    }
}

// ---------------------------------------------------------------------------
extern "C" void kernel_launch(void* const* d_in, const int* in_sizes, int n_in,
                              void* d_out, int out_size)
{
    (void)in_sizes; (void)n_in; (void)out_size;
    const float* x     = (const float*)d_in[0];
    const float* mask  = (const float*)d_in[1];
    const float* w_qkv = (const float*)d_in[2];
    const float* w_out = (const float*)d_in[3];
    const float* b_out = (const float*)d_in[4];
    float* out = (float*)d_out;

    float *qkv_ptr, *att_ptr;
    cudaGetSymbolAddress((void**)&qkv_ptr, g_qkv);
    cudaGetSymbolAddress((void**)&att_ptr, g_att);

    static_assert(sizeof(float) == 4, "");
    const int ATTN_SMEM = (3 * 8 * 512 + 512) * 4;   // 51200 B
    cudaFuncSetAttribute(attn_kernel,
                         cudaFuncAttributeMaxDynamicSharedMemorySize, ATTN_SMEM);

    dim3 blk(256);
    // 1) qkv = x @ w_qkv            [65536,512]x[512,1536]
    sgemm_kernel<false><<<dim3(INNER3 / 128, M_ROWS / 128), blk>>>(
        x, w_qkv, nullptr, qkv_ptr, M_ROWS, INNER3, DIM);
    // 2) per-pixel attention
    attn_kernel<<<N_PIX, blk, ATTN_SMEM>>>(qkv_ptr, mask, att_ptr);
    // 3) out = att @ w_out + b_out  [65536,512]x[512,512]
    sgemm_kernel<true><<<dim3(INNER / 128, M_ROWS / 128), blk>>>(
        att_ptr, w_out, b_out, out, M_ROWS, INNER, DIM);
}

// round 3
// speedup vs baseline: 2.4685x; 2.4685x over previous
#include <cuda_runtime.h>
#include <cstdint>
#include <math.h>

// ---------------------------------------------------------------- constants
#define N_PIX     8192
#define N_TOK     8
#define DIM       512
#define INNER     512
#define INNER3    1536
#define SCALE_F   0.125f
#define M_ROWS    65536

// GEMM tiling
#define BM     128
#define BN     128
#define BK     32
#define STAGES 3
#define TK     (DIM / BK)              // 16 K-tiles
#define APITCH 36                      // floats per row (bank: (4r+k)%32 bijective)
#define TILE_FLOATS (128 * APITCH)     // 4608 floats per operand tile
#define STAGE_FLOATS (2 * TILE_FLOATS) // A + B
#define GEMM_SMEM (STAGES * STAGE_FLOATS * 4)   // 110592 B

// Scratch (__device__ globals per allocation rules)
__device__ float g_qkv[(size_t)M_ROWS * INNER3];   // ~402 MB
__device__ float g_att[(size_t)M_ROWS * INNER];    // ~134 MB
__device__ float g_wqkvT[(size_t)INNER3 * DIM];    // 3 MB  [1536][512] K-major
__device__ float g_woutT[(size_t)INNER * DIM];     // 1 MB  [512][512]  K-major

// ---------------------------------------------------------------- helpers
__device__ __forceinline__ uint32_t smem_u32(const void* p) {
    uint32_t a;
    asm("{ .reg .u64 t; cvta.to.shared.u64 t, %1; cvt.u32.u64 %0, t; }"
        : "=r"(a) : "l"(p));
    return a;
}
__device__ __forceinline__ void cp16(uint32_t dst, const void* src) {
    asm volatile("cp.async.cg.shared.global [%0], [%1], 16;"
                 :: "r"(dst), "l"(src));
}
__device__ __forceinline__ void cp_commit() {
    asm volatile("cp.async.commit_group;" ::: "memory");
}
template <int N> __device__ __forceinline__ void cp_wait() {
    asm volatile("cp.async.wait_group %0;" :: "n"(N) : "memory");
}
__device__ __forceinline__ uint32_t f2tf(float f) {
    uint32_t u;
    asm("cvt.rna.tf32.f32 %0, %1;" : "=r"(u) : "f"(f));
    return u;
}
__device__ __forceinline__ void mma_tf32(float* c, uint32_t a0, uint32_t a1,
                                         uint32_t a2, uint32_t a3,
                                         uint32_t b0, uint32_t b1) {
    asm volatile(
        "mma.sync.aligned.m16n8k8.row.col.f32.tf32.tf32.f32 "
        "{%0,%1,%2,%3}, {%4,%5,%6,%7}, {%8,%9}, {%0,%1,%2,%3};"
        : "+f"(c[0]), "+f"(c[1]), "+f"(c[2]), "+f"(c[3])
        : "r"(a0), "r"(a1), "r"(a2), "r"(a3), "r"(b0), "r"(b1));
}

// ---------------------------------------------------------------- tf32 GEMM
// C[M, Ncols] = A[M, 512] @ Bt[Ncols, 512]^T (+bias)
// 256 threads = 8 warps in 2(m) x 4(n); warp tile 64x32; mma m16n8k8.
template <bool BIAS>
__global__ void __launch_bounds__(256)
gemm_tf32(const float* __restrict__ A, const float* __restrict__ Bt,
          const float* __restrict__ bias, float* __restrict__ C, int Ncols)
{
    extern __shared__ float sh[];
    const int tid  = threadIdx.x;
    const int wid  = tid >> 5, lane = tid & 31;
    const int g    = lane >> 2, tig = lane & 3;
    const int wm   = (wid >> 2) * 64;        // warp M offset (0 / 64)
    const int wn   = (wid & 3) * 32;         // warp N offset (0/32/64/96)
    const int bm   = blockIdx.y * BM;
    const int bn   = blockIdx.x * BN;
    const uint32_t sbase = smem_u32(sh);

    float c[4][4][4];                         // [mt][nt][frag]
#pragma unroll
    for (int i = 0; i < 4; i++)
#pragma unroll
        for (int j = 0; j < 4; j++)
#pragma unroll
            for (int q = 0; q < 4; q++) c[i][j][q] = 0.f;

    // loader: K-tile t -> stage slot s
    auto load_tile = [&](int t, int s) {
        uint32_t st = sbase + (uint32_t)(s * STAGE_FLOATS * 4);
        const float* Ab = A + (size_t)bm * DIM + t * BK;
#pragma unroll
        for (int i = 0; i < 4; i++) {         // 1024 chunks / 256 threads
            int id = tid + i * 256;
            int r = id >> 3, ck = id & 7;
            cp16(st + (uint32_t)(r * APITCH + ck * 4) * 4,
                 Ab + (size_t)r * DIM + ck * 4);
        }
        uint32_t stB = st + (uint32_t)TILE_FLOATS * 4;
        const float* Bb = Bt + (size_t)bn * DIM + t * BK;
#pragma unroll
        for (int i = 0; i < 4; i++) {
            int id = tid + i * 256;
            int r = id >> 3, ck = id & 7;
            cp16(stB + (uint32_t)(r * APITCH + ck * 4) * 4,
                 Bb + (size_t)r * DIM + ck * 4);
        }
    };

    load_tile(0, 0); cp_commit();
    load_tile(1, 1); cp_commit();

    for (int t = 0; t < TK; t++) {
        cp_wait<1>();
        __syncthreads();
        if (t + 2 < TK) { load_tile(t + 2, (t + 2) % STAGES); cp_commit(); }

        const float* As = sh + (size_t)(t % STAGES) * STAGE_FLOATS;
        const float* Bs = As + TILE_FLOATS;

#pragma unroll
        for (int ks = 0; ks < 4; ks++) {
            const int k0 = ks * 8;
            uint32_t af[4][4], bf[4][2];
#pragma unroll
            for (int mt = 0; mt < 4; mt++) {
                const float* ap = As + (wm + mt * 16 + g) * APITCH + k0 + tig;
                af[mt][0] = f2tf(ap[0]);
                af[mt][1] = f2tf(ap[8 * APITCH]);
                af[mt][2] = f2tf(ap[4]);
                af[mt][3] = f2tf(ap[8 * APITCH + 4]);
            }
#pragma unroll
            for (int nt = 0; nt < 4; nt++) {
                const float* bp = Bs + (wn + nt * 8 + g) * APITCH + k0 + tig;
                bf[nt][0] = f2tf(bp[0]);
                bf[nt][1] = f2tf(bp[4]);
            }
#pragma unroll
            for (int mt = 0; mt < 4; mt++)
#pragma unroll
                for (int nt = 0; nt < 4; nt++)
                    mma_tf32(c[mt][nt], af[mt][0], af[mt][1], af[mt][2],
                             af[mt][3], bf[nt][0], bf[nt][1]);
        }
        __syncthreads();
    }

    // epilogue: float2 stores (32B sectors fully used per row-group)
#pragma unroll
    for (int mt = 0; mt < 4; mt++) {
#pragma unroll
        for (int nt = 0; nt < 4; nt++) {
            int col = bn + wn + nt * 8 + 2 * tig;
            float b0 = 0.f, b1 = 0.f;
            if (BIAS) { b0 = bias[col]; b1 = bias[col + 1]; }
            int r0 = bm + wm + mt * 16 + g;
            float2 v0 = make_float2(c[mt][nt][0] + b0, c[mt][nt][1] + b1);
            float2 v1 = make_float2(c[mt][nt][2] + b0, c[mt][nt][3] + b1);
            *reinterpret_cast<float2*>(C + (size_t)r0 * Ncols + col) = v0;
            *reinterpret_cast<float2*>(C + (size_t)(r0 + 8) * Ncols + col) = v1;
        }
    }
}

// ---------------------------------------------------------------- transpose
__global__ void __launch_bounds__(256)
transpose_kernel(const float* __restrict__ in, float* __restrict__ out,
                 int R, int Ccols)
{
    __shared__ float tile[32][33];
    int c0 = blockIdx.x * 32, r0 = blockIdx.y * 32;
    int tx = threadIdx.x & 31, ty = threadIdx.x >> 5;
    for (int i = ty; i < 32; i += 8)
        tile[i][tx] = in[(size_t)(r0 + i) * Ccols + c0 + tx];
    __syncthreads();
    for (int i = ty; i < 32; i += 8)
        out[(size_t)(c0 + i) * R + r0 + tx] = tile[tx][i];
}

// ---------------------------------------------------------------- attention
__global__ void __launch_bounds__(256)
attn_kernel(const float* __restrict__ qkv, const float* __restrict__ mask,
            float* __restrict__ out)
{
    extern __shared__ float sh[];
    float* sq = sh;
    float* sk = sh + 4096;
    float* sv = sh + 8192;
    float* sd = sh + 12288;

    const int p   = blockIdx.x;
    const int tid = threadIdx.x;
    const float* base = qkv + (size_t)p * N_TOK * INNER3;

    for (int s = tid; s < 3072; s += 256) {
        int row = s / 384;
        int c4  = s % 384;
        float4 v = *reinterpret_cast<const float4*>(base + (size_t)row * INNER3 + c4 * 4);
        int col = c4 * 4;
        if (col < 512)       *reinterpret_cast<float4*>(&sq[row * 512 + col])        = v;
        else if (col < 1024) *reinterpret_cast<float4*>(&sk[row * 512 + col - 512])  = v;
        else                 *reinterpret_cast<float4*>(&sv[row * 512 + col - 1024]) = v;
    }
    __syncthreads();

    for (int s = tid; s < 512; s += 256) {
        int h = s >> 6, i = (s >> 3) & 7, j = s & 7;
        const float4* qp = reinterpret_cast<const float4*>(&sq[i * 512 + h * 64]);
        const float4* kp = reinterpret_cast<const float4*>(&sk[j * 512 + h * 64]);
        float acc = 0.f;
#pragma unroll
        for (int d = 0; d < 16; d++) {
            float4 a = qp[d], b = kp[d];
            acc += a.x * b.x + a.y * b.y + a.z * b.z + a.w * b.w;
        }
        float m = mask[(size_t)p * 64 + i * 8 + j];
        sd[(h * 8 + i) * 8 + j] = acc * SCALE_F * m;
    }
    __syncthreads();

    if (tid < 64) {
        int h = tid >> 3, i = tid & 7;
        float* row = &sd[(h * 8 + i) * 8];
        float mx = row[0];
#pragma unroll
        for (int j = 1; j < 8; j++) mx = fmaxf(mx, row[j]);
        float e[8], sum = 0.f;
#pragma unroll
        for (int j = 0; j < 8; j++) { e[j] = __expf(row[j] - mx); sum += e[j]; }
        float inv = 1.f / sum;
#pragma unroll
        for (int j = 0; j < 8; j++) row[j] = e[j] * inv;
    }
    __syncthreads();

    float* ob = out + (size_t)p * N_TOK * INNER;
    for (int s = tid; s < 1024; s += 256) {
        int i   = s >> 7;
        int c4  = s & 127;
        int col = c4 * 4;
        int h   = col >> 6;
        float4 acc = make_float4(0.f, 0.f, 0.f, 0.f);
#pragma unroll
        for (int j = 0; j < 8; j++) {
            float a = sd[(h * 8 + i) * 8 + j];
            float4 vv = *reinterpret_cast<const float4*>(&sv[j * 512 + col]);
            acc.x = fmaf(a, vv.x, acc.x);
            acc.y = fmaf(a, vv.y, acc.y);
            acc.z = fmaf(a, vv.z, acc.z);
            acc.w = fmaf(a, vv.w, acc.w);
        }
        *reinterpret_cast<float4*>(ob + (size_t)i * INNER + col) = acc;
    }
}

// ---------------------------------------------------------------- launch
extern "C" void kernel_launch(void* const* d_in, const int* in_sizes, int n_in,
                              void* d_out, int out_size)
{
    (void)in_sizes; (void)n_in; (void)out_size;
    const float* x     = (const float*)d_in[0];
    const float* mask  = (const float*)d_in[1];
    const float* w_qkv = (const float*)d_in[2];
    const float* w_out = (const float*)d_in[3];
    const float* b_out = (const float*)d_in[4];
    float* out = (float*)d_out;

    float *qkv_p, *att_p, *wqkvT_p, *woutT_p;
    cudaGetSymbolAddress((void**)&qkv_p, g_qkv);
    cudaGetSymbolAddress((void**)&att_p, g_att);
    cudaGetSymbolAddress((void**)&wqkvT_p, g_wqkvT);
    cudaGetSymbolAddress((void**)&woutT_p, g_woutT);

    cudaFuncSetAttribute(gemm_tf32<false>,
                         cudaFuncAttributeMaxDynamicSharedMemorySize, GEMM_SMEM);
    cudaFuncSetAttribute(gemm_tf32<true>,
                         cudaFuncAttributeMaxDynamicSharedMemorySize, GEMM_SMEM);
    const int ATTN_SMEM = (3 * 8 * 512 + 512) * 4;
    cudaFuncSetAttribute(attn_kernel,
                         cudaFuncAttributeMaxDynamicSharedMemorySize, ATTN_SMEM);

    // weight transposes to K-major [N][K]
    transpose_kernel<<<dim3(INNER3 / 32, DIM / 32), 256>>>(w_qkv, wqkvT_p, DIM, INNER3);
    transpose_kernel<<<dim3(INNER  / 32, DIM / 32), 256>>>(w_out, woutT_p, DIM, INNER);

    // 1) qkv = x @ w_qkv
    gemm_tf32<false><<<dim3(INNER3 / BN, M_ROWS / BM), 256, GEMM_SMEM>>>(
        x, wqkvT_p, nullptr, qkv_p, INNER3);
    // 2) attention
    attn_kernel<<<N_PIX, 256, ATTN_SMEM>>>(qkv_p, mask, att_p);
    // 3) out = att @ w_out + b_out
    gemm_tf32<true><<<dim3(INNER / BN, M_ROWS / BM), 256, GEMM_SMEM>>>(
        att_p, woutT_p, b_out, out, INNER);
}

// round 4
// speedup vs baseline: 3.1366x; 1.2706x over previous
#include <cuda_runtime.h>
#include <cstdint>
#include <math.h>

// ---------------------------------------------------------------- constants
#define N_PIX     8192
#define N_TOK     8
#define DIM       512
#define INNER     512
#define INNER3    1536
#define SCALE_F   0.125f
#define M_ROWS    65536

// GEMM tiling
#define BM     128
#define BN     128
#define BK     32
#define STAGES 3
#define TK     (DIM / BK)              // 16 K-tiles
#define APITCH 36
#define TILE_FLOATS (128 * APITCH)
#define STAGE_FLOATS (2 * TILE_FLOATS)
#define GEMM_SMEM (STAGES * STAGE_FLOATS * 4)   // 110592 B

// attention smem pitch: 516 floats -> row-to-row bank offset 4, 16B aligned
#define QPITCH 516

// Scratch (__device__ globals per allocation rules)
__device__ float g_qkv[(size_t)M_ROWS * INNER3];   // ~402 MB
__device__ float g_att[(size_t)M_ROWS * INNER];    // ~134 MB (tf32-rounded)
__device__ float g_xtf[(size_t)M_ROWS * DIM];      // ~134 MB (tf32-rounded x)
__device__ float g_wqkvT[(size_t)INNER3 * DIM];    // K-major, tf32-rounded
__device__ float g_woutT[(size_t)INNER * DIM];     // K-major, tf32-rounded

// ---------------------------------------------------------------- helpers
__device__ __forceinline__ uint32_t smem_u32(const void* p) {
    uint32_t a;
    asm("{ .reg .u64 t; cvta.to.shared.u64 t, %1; cvt.u32.u64 %0, t; }"
        : "=r"(a) : "l"(p));
    return a;
}
__device__ __forceinline__ void cp16(uint32_t dst, const void* src) {
    asm volatile("cp.async.cg.shared.global [%0], [%1], 16;"
                 :: "r"(dst), "l"(src));
}
__device__ __forceinline__ void cp_commit() {
    asm volatile("cp.async.commit_group;" ::: "memory");
}
template <int N> __device__ __forceinline__ void cp_wait() {
    asm volatile("cp.async.wait_group %0;" :: "n"(N) : "memory");
}
__device__ __forceinline__ uint32_t f2tf(float f) {
    uint32_t u;
    asm("cvt.rna.tf32.f32 %0, %1;" : "=r"(u) : "f"(f));
    return u;
}
__device__ __forceinline__ float rtf(float f) {      // round-to-tf32, as float
    return __uint_as_float(f2tf(f));
}
__device__ __forceinline__ void mma_tf32(float* c, uint32_t a0, uint32_t a1,
                                         uint32_t a2, uint32_t a3,
                                         uint32_t b0, uint32_t b1) {
    asm volatile(
        "mma.sync.aligned.m16n8k8.row.col.f32.tf32.tf32.f32 "
        "{%0,%1,%2,%3}, {%4,%5,%6,%7}, {%8,%9}, {%0,%1,%2,%3};"
        : "+f"(c[0]), "+f"(c[1]), "+f"(c[2]), "+f"(c[3])
        : "r"(a0), "r"(a1), "r"(a2), "r"(a3), "r"(b0), "r"(b1));
}

// ---------------------------------------------------------------- tf32 GEMM
// Operands are PRE-ROUNDED to tf32 bit patterns; mainloop has zero CVTs.
template <bool BIAS>
__global__ void __launch_bounds__(256)
gemm_tf32(const float* __restrict__ A, const float* __restrict__ Bt,
          const float* __restrict__ bias, float* __restrict__ C, int Ncols)
{
    extern __shared__ float sh[];
    const int tid  = threadIdx.x;
    const int wid  = tid >> 5, lane = tid & 31;
    const int g    = lane >> 2, tig = lane & 3;
    const int wm   = (wid >> 2) * 64;
    const int wn   = (wid & 3) * 32;
    const int bm   = blockIdx.y * BM;
    const int bn   = blockIdx.x * BN;
    const uint32_t sbase = smem_u32(sh);

    float c[4][4][4];
#pragma unroll
    for (int i = 0; i < 4; i++)
#pragma unroll
        for (int j = 0; j < 4; j++)
#pragma unroll
            for (int q = 0; q < 4; q++) c[i][j][q] = 0.f;

    auto load_tile = [&](int t, int s) {
        uint32_t st = sbase + (uint32_t)(s * STAGE_FLOATS * 4);
        const float* Ab = A + (size_t)bm * DIM + t * BK;
#pragma unroll
        for (int i = 0; i < 4; i++) {
            int id = tid + i * 256;
            int r = id >> 3, ck = id & 7;
            cp16(st + (uint32_t)(r * APITCH + ck * 4) * 4,
                 Ab + (size_t)r * DIM + ck * 4);
        }
        uint32_t stB = st + (uint32_t)TILE_FLOATS * 4;
        const float* Bb = Bt + (size_t)bn * DIM + t * BK;
#pragma unroll
        for (int i = 0; i < 4; i++) {
            int id = tid + i * 256;
            int r = id >> 3, ck = id & 7;
            cp16(stB + (uint32_t)(r * APITCH + ck * 4) * 4,
                 Bb + (size_t)r * DIM + ck * 4);
        }
    };

    load_tile(0, 0); cp_commit();
    load_tile(1, 1); cp_commit();

    for (int t = 0; t < TK; t++) {
        cp_wait<1>();
        __syncthreads();
        if (t + 2 < TK) { load_tile(t + 2, (t + 2) % STAGES); cp_commit(); }

        const float* As = sh + (size_t)(t % STAGES) * STAGE_FLOATS;
        const float* Bs = As + TILE_FLOATS;

#pragma unroll
        for (int ks = 0; ks < 4; ks++) {
            const int k0 = ks * 8;
            uint32_t af[4][4], bf[4][2];
#pragma unroll
            for (int mt = 0; mt < 4; mt++) {
                const float* ap = As + (wm + mt * 16 + g) * APITCH + k0 + tig;
                af[mt][0] = __float_as_uint(ap[0]);
                af[mt][1] = __float_as_uint(ap[8 * APITCH]);
                af[mt][2] = __float_as_uint(ap[4]);
                af[mt][3] = __float_as_uint(ap[8 * APITCH + 4]);
            }
#pragma unroll
            for (int nt = 0; nt < 4; nt++) {
                const float* bp = Bs + (wn + nt * 8 + g) * APITCH + k0 + tig;
                bf[nt][0] = __float_as_uint(bp[0]);
                bf[nt][1] = __float_as_uint(bp[4]);
            }
#pragma unroll
            for (int mt = 0; mt < 4; mt++)
#pragma unroll
                for (int nt = 0; nt < 4; nt++)
                    mma_tf32(c[mt][nt], af[mt][0], af[mt][1], af[mt][2],
                             af[mt][3], bf[nt][0], bf[nt][1]);
        }
        __syncthreads();
    }

#pragma unroll
    for (int mt = 0; mt < 4; mt++) {
#pragma unroll
        for (int nt = 0; nt < 4; nt++) {
            int col = bn + wn + nt * 8 + 2 * tig;
            float b0 = 0.f, b1 = 0.f;
            if (BIAS) { b0 = bias[col]; b1 = bias[col + 1]; }
            int r0 = bm + wm + mt * 16 + g;
            float2 v0 = make_float2(c[mt][nt][0] + b0, c[mt][nt][1] + b1);
            float2 v1 = make_float2(c[mt][nt][2] + b0, c[mt][nt][3] + b1);
            *reinterpret_cast<float2*>(C + (size_t)r0 * Ncols + col) = v0;
            *reinterpret_cast<float2*>(C + (size_t)(r0 + 8) * Ncols + col) = v1;
        }
    }
}

// ---------------------------------------------------------------- pre-round
__global__ void __launch_bounds__(256)
round_kernel(const float* __restrict__ in, float* __restrict__ out, size_t n4)
{
    size_t i = (size_t)blockIdx.x * blockDim.x + threadIdx.x;
    if (i >= n4) return;
    float4 v = reinterpret_cast<const float4*>(in)[i];
    v.x = rtf(v.x); v.y = rtf(v.y); v.z = rtf(v.z); v.w = rtf(v.w);
    reinterpret_cast<float4*>(out)[i] = v;
}

// ---------------------------------------------------------------- transpose (+tf32 round)
__global__ void __launch_bounds__(256)
transpose_kernel(const float* __restrict__ in, float* __restrict__ out,
                 int R, int Ccols)
{
    __shared__ float tile[32][33];
    int c0 = blockIdx.x * 32, r0 = blockIdx.y * 32;
    int tx = threadIdx.x & 31, ty = threadIdx.x >> 5;
    for (int i = ty; i < 32; i += 8)
        tile[i][tx] = rtf(in[(size_t)(r0 + i) * Ccols + c0 + tx]);
    __syncthreads();
    for (int i = ty; i < 32; i += 8)
        out[(size_t)(c0 + i) * R + r0 + tx] = tile[tx][i];
}

// ---------------------------------------------------------------- attention
// smem rows padded to QPITCH=516 floats -> conflict-free k-row reads in dots.
// Output is tf32-rounded (feeds GEMM2 directly).
__global__ void __launch_bounds__(256)
attn_kernel(const float* __restrict__ qkv, const float* __restrict__ mask,
            float* __restrict__ out)
{
    extern __shared__ float sh[];
    float* sq = sh;                      // [8][QPITCH]
    float* sk = sh + 8 * QPITCH;
    float* sv = sh + 16 * QPITCH;
    float* sd = sh + 24 * QPITCH;        // [8][8][8]

    const int p   = blockIdx.x;
    const int tid = threadIdx.x;
    const float* base = qkv + (size_t)p * N_TOK * INNER3;

    for (int s = tid; s < 3072; s += 256) {
        int row = s / 384;
        int c4  = s % 384;
        float4 v = *reinterpret_cast<const float4*>(base + (size_t)row * INNER3 + c4 * 4);
        int col = c4 * 4;
        if (col < 512)
            *reinterpret_cast<float4*>(&sq[row * QPITCH + col]) = v;
        else if (col < 1024)
            *reinterpret_cast<float4*>(&sk[row * QPITCH + col - 512]) = v;
        else
            *reinterpret_cast<float4*>(&sv[row * QPITCH + col - 1024]) = v;
    }
    __syncthreads();

    for (int s = tid; s < 512; s += 256) {
        int h = s >> 6, i = (s >> 3) & 7, j = s & 7;
        const float4* qp = reinterpret_cast<const float4*>(&sq[i * QPITCH + h * 64]);
        const float4* kp = reinterpret_cast<const float4*>(&sk[j * QPITCH + h * 64]);
        float acc = 0.f;
#pragma unroll
        for (int d = 0; d < 16; d++) {
            float4 a = qp[d], b = kp[d];
            acc += a.x * b.x + a.y * b.y + a.z * b.z + a.w * b.w;
        }
        float m = mask[(size_t)p * 64 + i * 8 + j];
        sd[(h * 8 + i) * 8 + j] = acc * SCALE_F * m;
    }
    __syncthreads();

    if (tid < 64) {
        int h = tid >> 3, i = tid & 7;
        float* row = &sd[(h * 8 + i) * 8];
        float mx = row[0];
#pragma unroll
        for (int j = 1; j < 8; j++) mx = fmaxf(mx, row[j]);
        float e[8], sum = 0.f;
#pragma unroll
        for (int j = 0; j < 8; j++) { e[j] = __expf(row[j] - mx); sum += e[j]; }
        float inv = 1.f / sum;
#pragma unroll
        for (int j = 0; j < 8; j++) row[j] = e[j] * inv;
    }
    __syncthreads();

    float* ob = out + (size_t)p * N_TOK * INNER;
    for (int s = tid; s < 1024; s += 256) {
        int i   = s >> 7;
        int c4  = s & 127;
        int col = c4 * 4;
        int h   = col >> 6;
        float4 acc = make_float4(0.f, 0.f, 0.f, 0.f);
#pragma unroll
        for (int j = 0; j < 8; j++) {
            float a = sd[(h * 8 + i) * 8 + j];
            float4 vv = *reinterpret_cast<const float4*>(&sv[j * QPITCH + col]);
            acc.x = fmaf(a, vv.x, acc.x);
            acc.y = fmaf(a, vv.y, acc.y);
            acc.z = fmaf(a, vv.z, acc.z);
            acc.w = fmaf(a, vv.w, acc.w);
        }
        acc.x = rtf(acc.x); acc.y = rtf(acc.y);
        acc.z = rtf(acc.z); acc.w = rtf(acc.w);
        *reinterpret_cast<float4*>(ob + (size_t)i * INNER + col) = acc;
    }
}

// ---------------------------------------------------------------- launch
extern "C" void kernel_launch(void* const* d_in, const int* in_sizes, int n_in,
                              void* d_out, int out_size)
{
    (void)in_sizes; (void)n_in; (void)out_size;
    const float* x     = (const float*)d_in[0];
    const float* mask  = (const float*)d_in[1];
    const float* w_qkv = (const float*)d_in[2];
    const float* w_out = (const float*)d_in[3];
    const float* b_out = (const float*)d_in[4];
    float* out = (float*)d_out;

    float *qkv_p, *att_p, *xtf_p, *wqkvT_p, *woutT_p;
    cudaGetSymbolAddress((void**)&qkv_p, g_qkv);
    cudaGetSymbolAddress((void**)&att_p, g_att);
    cudaGetSymbolAddress((void**)&xtf_p, g_xtf);
    cudaGetSymbolAddress((void**)&wqkvT_p, g_wqkvT);
    cudaGetSymbolAddress((void**)&woutT_p, g_woutT);

    cudaFuncSetAttribute(gemm_tf32<false>,
                         cudaFuncAttributeMaxDynamicSharedMemorySize, GEMM_SMEM);
    cudaFuncSetAttribute(gemm_tf32<true>,
                         cudaFuncAttributeMaxDynamicSharedMemorySize, GEMM_SMEM);
    const int ATTN_SMEM = (24 * QPITCH + 512) * 4;   // 51584 B
    cudaFuncSetAttribute(attn_kernel,
                         cudaFuncAttributeMaxDynamicSharedMemorySize, ATTN_SMEM);

    // pre-round x, weights (fused into transpose)
    const size_t n4 = (size_t)M_ROWS * DIM / 4;
    round_kernel<<<(unsigned)((n4 + 255) / 256), 256>>>(x, xtf_p, n4);
    transpose_kernel<<<dim3(INNER3 / 32, DIM / 32), 256>>>(w_qkv, wqkvT_p, DIM, INNER3);
    transpose_kernel<<<dim3(INNER  / 32, DIM / 32), 256>>>(w_out, woutT_p, DIM, INNER);

    // 1) qkv = x @ w_qkv
    gemm_tf32<false><<<dim3(INNER3 / BN, M_ROWS / BM), 256, GEMM_SMEM>>>(
        xtf_p, wqkvT_p, nullptr, qkv_p, INNER3);
    // 2) attention (writes tf32-rounded att)
    attn_kernel<<<N_PIX, 256, ATTN_SMEM>>>(qkv_p, mask, att_p);
    // 3) out = att @ w_out + b_out
    gemm_tf32<true><<<dim3(INNER / BN, M_ROWS / BM), 256, GEMM_SMEM>>>(
        att_p, woutT_p, b_out, out, INNER);
}